// round 6
// baseline (speedup 1.0000x reference)
#include <cuda_runtime.h>
#include <cuda_bf16.h>
#include <math.h>

#define BB 4
#define HH 512
#define WW 512
#define NPIX (BB*HH*WW)
#define TW 32
#define TH 8

#define TAUc   0.01f
#define RHOc   1.99f
#define SIGMAc 1.3888888888888888f   // 1/0.01/72

// u2: 4x bf16 (uint2). r2/rbar: 2x bf16 (u32). x2/xbar: fp32.
typedef uint2 U2raw;
__device__ __align__(16) float    g_x2  [NPIX];
__device__ __align__(16) unsigned g_r2  [NPIX];
__device__ __align__(16) U2raw    g_u2  [NPIX];
__device__ __align__(16) float    g_xbar[NPIX];
__device__ __align__(16) unsigned g_rbar[NPIX];

static __device__ __forceinline__ float4 u2unpack(U2raw r) {
    float2 f0 = __bfloat1622float2(*reinterpret_cast<__nv_bfloat162*>(&r.x));
    float2 f1 = __bfloat1622float2(*reinterpret_cast<__nv_bfloat162*>(&r.y));
    return make_float4(f0.x, f0.y, f1.x, f1.y);
}
static __device__ __forceinline__ U2raw u2pack(float a, float b, float c, float d) {
    __nv_bfloat162 p0 = __floats2bfloat162_rn(a, b);
    __nv_bfloat162 p1 = __floats2bfloat162_rn(c, d);
    U2raw r;
    r.x = *reinterpret_cast<unsigned*>(&p0);
    r.y = *reinterpret_cast<unsigned*>(&p1);
    return r;
}
static __device__ __forceinline__ float2 bf2unpack(unsigned r) {
    return __bfloat1622float2(*reinterpret_cast<__nv_bfloat162*>(&r));
}
static __device__ __forceinline__ unsigned bf2pack(float a, float b) {
    __nv_bfloat162 p = __floats2bfloat162_rn(a, b);
    return *reinterpret_cast<unsigned*>(&p);
}
static __device__ __forceinline__ float ldc(const U2raw* b, int h, int w, int comp) {
    if ((unsigned)h < HH && (unsigned)w < WW) {
        const __nv_bfloat16* p = reinterpret_cast<const __nv_bfloat16*>(b + h * WW + w);
        return __bfloat162float(__ldg(p + comp));
    }
    return 0.f;
}

// ---------------------------------------------------------------------------
// Kernel A: each thread computes ONLY its own tmp pair (t0p, t1p); left/up
// neighbors come from shared memory (block-edge threads compute the halo).
// Then x-prox + r-prox + relaxation. r2/rbar in bf16x2.
// Relies on zero-padding + invariants u2.y==0 at w=0, u2.w==0 at h=H-1.
// ---------------------------------------------------------------------------
template<bool LAST>
__global__ void __launch_bounds__(TW*TH)
k_A(const float* __restrict__ y, const int* __restrict__ ths,
    float* __restrict__ outx) {
    __shared__ float st0[TH][TW + 1];      // tmp0 at cols w0-1 .. w0+TW-1
    __shared__ float st1[TH + 1][TW];      // tmp1 at rows h0-1 .. h0+TH-1

    const int tx = threadIdx.x, ty = threadIdx.y;
    const int w = blockIdx.x * TW + tx;
    const int h = blockIdx.y * TH + ty;
    const int b = blockIdx.z;
    const int i = (b * HH + h) * WW + w;
    const U2raw* u2b = g_u2 + (size_t)b * HH * WW;

    const float4 c = u2unpack(__ldg(u2b + h * WW + w));

    float rty = 0.f, rtz = 0.f;
    if (w < WW - 1) {
        float4 rf = u2unpack(__ldg(u2b + h * WW + w + 1));
        rty = rf.y; rtz = rf.z;
    }
    float upz = 0.f, upw = 0.f;
    if (h > 0) {
        float2 f = bf2unpack(__ldg(&(u2b + (h - 1) * WW + w)->y));
        upz = f.x; upw = f.y;
    }
    const float Xd = ldc(u2b, h + 1, w, 0);

    const float t0p = TAUc * (c.x - Xd - rty + c.y);
    const float t1p = TAUc * (c.z - rtz - c.w + upw);
    st0[ty][tx + 1] = t0p;
    st1[ty + 1][tx] = t1p;

    if (tx == 0) {
        float lx = 0.f, ly = 0.f, Xdl = 0.f;
        if (w > 0) {
            float2 f = bf2unpack(__ldg(&(u2b + h * WW + w - 1)->x));
            lx = f.x; ly = f.y;
            Xdl = ldc(u2b, h + 1, w - 1, 0);
        }
        st0[ty][0] = TAUc * (lx - Xdl - c.y + ly);
    }
    if (ty == 0) {
        const float Zur = ldc(u2b, h - 1, w + 1, 2);
        const float Wu2 = ldc(u2b, h - 2, w, 3);
        st1[0][tx] = TAUc * (upz - Zur - upw + Wu2);
    }
    __syncthreads();

    const float t0l = st0[ty][tx];
    const float t1u = st1[ty][tx];

    float div = 0.f;
    if (w < WW - 1) div -= t0p;
    if (w > 0)      div += t0l;
    if (h < HH - 1) div -= t1p;
    if (h > 0)      div += t1u;

    const float x2o = __ldg(&g_x2[i]);
    const float x = (x2o - div + TAUc * __ldg(&y[i])) * (1.f / (1.f + TAUc));
    const float x2n = x2o + RHOc * (x - x2o);

    if (LAST) { outx[i] = x2n; return; }

    g_xbar[i] = 2.f * x - x2o;
    g_x2[i]   = x2n;

    const float lam1 = 0.1f * (float)__ldg(ths);
    const float2 r2o = bf2unpack(__ldg(&g_r2[i]));
    const float rvx = r2o.x + t0p;
    const float rvy = r2o.y + t1p;
    const float nrm = sqrtf(rvx * rvx + rvy * rvy);
    const float s = 1.f - 1.f / fmaxf(nrm * (1.f / (TAUc * lam1)), 1.f);
    const float rx = rvx * s, ry = rvy * s;

    g_rbar[i] = bf2pack(2.f * rx - r2o.x, 2.f * ry - r2o.y);
    g_r2[i]   = bf2pack(r2o.x + RHOc * (rx - r2o.x),
                        r2o.y + RHOc * (ry - r2o.y));
}

// ---------------------------------------------------------------------------
// Kernel B: v = nabla2(xbar) - rbar in shared, then
// u = prox_sigma_g_conj(u2 + SIGMA*eps2(v)) + relaxation (u2/rbar in bf16).
// FIRST iteration: xbar == y, rbar == 0, u2 == 0; also initializes x2=y, r2=0.
// ---------------------------------------------------------------------------
template<bool FIRST>
__global__ void __launch_bounds__(TW*TH)
k_B(const float* __restrict__ y, const int* __restrict__ ths) {
    __shared__ float  sx[TH + 3][TW + 3];
    __shared__ float2 sv[TH + 2][TW + 2];

    const int tx = threadIdx.x, ty = threadIdx.y;
    const int tid = ty * TW + tx;
    const int w0 = blockIdx.x * TW, h0 = blockIdx.y * TH, b = blockIdx.z;
    const size_t boff = (size_t)b * HH * WW;
    const float* xb = FIRST ? (y + boff) : (g_xbar + boff);

    #pragma unroll
    for (int idx = tid; idx < (TH + 3) * (TW + 2); idx += TW * TH) {
        int rr = idx / (TW + 2), cc = idx % (TW + 2);
        int gh = h0 + rr - 1, gw = w0 + cc - 1;
        float v = 0.f;
        if (gh >= 0 && gh < HH && gw >= 0 && gw < WW) v = __ldg(xb + gh * WW + gw);
        sx[rr][cc] = v;
    }
    __syncthreads();

    #pragma unroll
    for (int idx = tid; idx < (TH + 2) * (TW + 1); idx += TW * TH) {
        int R = idx / (TW + 1), C = idx % (TW + 1);
        int gh = h0 + R - 1, gw = w0 + C - 1;
        float2 v = make_float2(0.f, 0.f);
        if (gh >= 0 && gh < HH && gw >= 0 && gw < WW) {
            float xc = sx[R][C];
            float v0 = (gw < WW - 1) ? (sx[R][C + 1] - xc) : 0.f;
            float v1 = (gh < HH - 1) ? (sx[R + 1][C] - xc) : 0.f;
            if (!FIRST) {
                float2 rb = bf2unpack(__ldg(&g_rbar[boff + gh * WW + gw]));
                v0 -= rb.x; v1 -= rb.y;
            }
            v = make_float2(v0, v1);
        }
        sv[R][C] = v;
    }
    __syncthreads();

    const int h = h0 + ty, w = w0 + tx;
    const int i = (int)boff + h * WW + w;

    float2 vc = sv[ty + 1][tx + 1];
    float2 vu = sv[ty][tx + 1];
    float2 vl = sv[ty + 1][tx];
    float2 vd = sv[ty + 2][tx + 1];

    float G0 = vc.x - vu.x;
    float G1 = (w > 0) ? (vc.x - vl.x) : 0.f;
    float G2 = vc.y - vl.y;
    float G3 = (h < HH - 1) ? (vd.y - vc.y) : 0.f;

    float4 u2o = FIRST ? make_float4(0.f, 0.f, 0.f, 0.f)
                       : u2unpack(__ldg(&g_u2[i]));
    float u0 = u2o.x + SIGMAc * G0;
    float u1 = u2o.y + SIGMAc * G1;
    float u2c = u2o.z + SIGMAc * G2;
    float u3 = u2o.w + SIGMAc * G3;

    float lam2 = 0.15f * (float)__ldg(ths);
    float nrm = sqrtf(u0 * u0 + u1 * u1 + u2c * u2c + u3 * u3);
    float sc = 1.f / fmaxf(nrm * (1.f / lam2), 1.f);
    u0 *= sc; u1 *= sc; u2c *= sc; u3 *= sc;

    g_u2[i] = u2pack(u2o.x + RHOc * (u0  - u2o.x),
                     u2o.y + RHOc * (u1  - u2o.y),
                     u2o.z + RHOc * (u2c - u2o.z),
                     u2o.w + RHOc * (u3  - u2o.w));

    if (FIRST) {
        g_x2[i] = sx[ty + 1][tx + 1];
        g_r2[i] = 0u;
    }
}

extern "C" void kernel_launch(void* const* d_in, const int* in_sizes, int n_in,
                              void* d_out, int out_size) {
    const float* y   = (const float*)d_in[0];
    const int*   ths = (const int*)d_in[1];
    float*       out = (float*)d_out;

    dim3 blk(TW, TH, 1);
    dim3 grd(WW / TW, HH / TH, BB);

    // Iteration 1 (specialized: A is a no-op closed form)
    k_B<true><<<grd, blk>>>(y, ths);

    // Iterations 2..9
    for (int it = 1; it < 9; ++it) {
        k_A<false><<<grd, blk>>>(y, ths, nullptr);
        k_B<false><<<grd, blk>>>(y, ths);
    }

    // Iteration 10: only the x path matters; write straight to output.
    k_A<true><<<grd, blk>>>(y, ths, out);
}

// round 7
// speedup vs baseline: 1.0101x; 1.0101x over previous
#include <cuda_runtime.h>
#include <cuda_bf16.h>
#include <math.h>

#define BB 4
#define HH 512
#define WW 512
#define NPIX (BB*HH*WW)
#define TW 32
#define TH 8

#define TAUc   0.01f
#define RHOc   1.99f
#define SIGMAc 1.3888888888888888f   // 1/0.01/72

// u2: 4x bf16 (uint2). r2/rbar: 2x bf16 (u32). x2/xbar: fp32.
typedef uint2 U2raw;
__device__ __align__(16) float    g_x2  [NPIX];
__device__ __align__(16) unsigned g_r2  [NPIX];
__device__ __align__(16) U2raw    g_u2  [NPIX];
__device__ __align__(16) float    g_xbar[NPIX];
__device__ __align__(16) unsigned g_rbar[NPIX];

static __device__ __forceinline__ float4 u2unpack(U2raw r) {
    float2 f0 = __bfloat1622float2(*reinterpret_cast<__nv_bfloat162*>(&r.x));
    float2 f1 = __bfloat1622float2(*reinterpret_cast<__nv_bfloat162*>(&r.y));
    return make_float4(f0.x, f0.y, f1.x, f1.y);
}
static __device__ __forceinline__ U2raw u2pack(float a, float b, float c, float d) {
    __nv_bfloat162 p0 = __floats2bfloat162_rn(a, b);
    __nv_bfloat162 p1 = __floats2bfloat162_rn(c, d);
    U2raw r;
    r.x = *reinterpret_cast<unsigned*>(&p0);
    r.y = *reinterpret_cast<unsigned*>(&p1);
    return r;
}
static __device__ __forceinline__ float2 bf2unpack(unsigned r) {
    return __bfloat1622float2(*reinterpret_cast<__nv_bfloat162*>(&r));
}
static __device__ __forceinline__ unsigned bf2pack(float a, float b) {
    __nv_bfloat162 p = __floats2bfloat162_rn(a, b);
    return *reinterpret_cast<unsigned*>(&p);
}
static __device__ __forceinline__ float ldc(const U2raw* b, int h, int w, int comp) {
    if ((unsigned)h < HH && (unsigned)w < WW) {
        const __nv_bfloat16* p = reinterpret_cast<const __nv_bfloat16*>(b + h * WW + w);
        return __bfloat162float(__ldg(p + comp));
    }
    return 0.f;
}

// ---------------------------------------------------------------------------
// Kernel A: per-thread tmp (t0p,t1p) from 6 u2 loads; t0l via warp shuffle
// (warp == image row), t1u recomputed in registers. NO block barrier.
// Then x-prox + r-prox + relaxation. r2/rbar in bf16x2.
// Relies on zero-padding + invariants u2.y==0 at w=0, u2.w==0 at h=H-1.
// ---------------------------------------------------------------------------
template<bool LAST>
__global__ void __launch_bounds__(TW*TH)
k_A(const float* __restrict__ y, const int* __restrict__ ths,
    float* __restrict__ outx) {
    const int tx = threadIdx.x;
    const int w = blockIdx.x * TW + tx;
    const int h = blockIdx.y * TH + threadIdx.y;
    const int b = blockIdx.z;
    const int i = (b * HH + h) * WW + w;
    const U2raw* p = g_u2 + (size_t)b * HH * WW + h * WW + w;
    const U2raw* u2b = g_u2 + (size_t)b * HH * WW;

    const float4 c = u2unpack(__ldg(p));

    float rty = 0.f, rtz = 0.f;
    if (w < WW - 1) {
        float4 rf = u2unpack(__ldg(p + 1));
        rty = rf.y; rtz = rf.z;
    }
    float upz = 0.f, upw = 0.f;
    if (h > 0) {
        float2 f = bf2unpack(__ldg(&(p - WW)->y));
        upz = f.x; upw = f.y;
    }
    const float Xd  = ldc(u2b, h + 1, w,     0);
    const float Zur = ldc(u2b, h - 1, w + 1, 2);
    const float Wu2 = ldc(u2b, h - 2, w,     3);

    const float t0p = TAUc * (c.x - Xd  - rty + c.y);
    const float t1p = TAUc * (c.z - rtz - c.w + upw);
    const float t1u = TAUc * (upz - Zur - upw + Wu2);

    float t0l = __shfl_up_sync(0xffffffffu, t0p, 1);
    if (tx == 0) {
        float lx = 0.f, ly = 0.f, Xdl = 0.f;
        if (w > 0) {
            float2 f = bf2unpack(__ldg(&(p - 1)->x));
            lx = f.x; ly = f.y;
            Xdl = ldc(u2b, h + 1, w - 1, 0);
        }
        t0l = TAUc * (lx - Xdl - c.y + ly);
    }

    float div = 0.f;
    if (w < WW - 1) div -= t0p;
    if (w > 0)      div += t0l;
    if (h < HH - 1) div -= t1p;
    if (h > 0)      div += t1u;

    const float x2o = __ldg(&g_x2[i]);
    const float x = (x2o - div + TAUc * __ldg(&y[i])) * (1.f / (1.f + TAUc));
    const float x2n = x2o + RHOc * (x - x2o);

    if (LAST) { outx[i] = x2n; return; }

    g_xbar[i] = 2.f * x - x2o;
    g_x2[i]   = x2n;

    const float lam1 = 0.1f * (float)__ldg(ths);
    const float2 r2o = bf2unpack(__ldg(&g_r2[i]));
    const float rvx = r2o.x + t0p;
    const float rvy = r2o.y + t1p;
    const float nrm = sqrtf(rvx * rvx + rvy * rvy);
    const float s = 1.f - 1.f / fmaxf(nrm * (1.f / (TAUc * lam1)), 1.f);
    const float rx = rvx * s, ry = rvy * s;

    g_rbar[i] = bf2pack(2.f * rx - r2o.x, 2.f * ry - r2o.y);
    g_r2[i]   = bf2pack(r2o.x + RHOc * (rx - r2o.x),
                        r2o.y + RHOc * (ry - r2o.y));
}

// ---------------------------------------------------------------------------
// Kernel B: v = nabla2(xbar) - rbar in shared, then
// u = prox_sigma_g_conj(u2 + SIGMA*eps2(v)) + relaxation (u2/rbar in bf16).
// FIRST iteration: xbar == y, rbar == 0, u2 == 0; also initializes x2=y, r2=0.
// ---------------------------------------------------------------------------
template<bool FIRST>
__global__ void __launch_bounds__(TW*TH)
k_B(const float* __restrict__ y, const int* __restrict__ ths) {
    __shared__ float  sx[TH + 3][TW + 3];
    __shared__ float2 sv[TH + 2][TW + 2];

    const int tx = threadIdx.x, ty = threadIdx.y;
    const int tid = ty * TW + tx;
    const int w0 = blockIdx.x * TW, h0 = blockIdx.y * TH, b = blockIdx.z;
    const size_t boff = (size_t)b * HH * WW;
    const float* xb = FIRST ? (y + boff) : (g_xbar + boff);

    #pragma unroll
    for (int idx = tid; idx < (TH + 3) * (TW + 2); idx += TW * TH) {
        int rr = idx / (TW + 2), cc = idx % (TW + 2);
        int gh = h0 + rr - 1, gw = w0 + cc - 1;
        float v = 0.f;
        if (gh >= 0 && gh < HH && gw >= 0 && gw < WW) v = __ldg(xb + gh * WW + gw);
        sx[rr][cc] = v;
    }
    __syncthreads();

    #pragma unroll
    for (int idx = tid; idx < (TH + 2) * (TW + 1); idx += TW * TH) {
        int R = idx / (TW + 1), C = idx % (TW + 1);
        int gh = h0 + R - 1, gw = w0 + C - 1;
        float2 v = make_float2(0.f, 0.f);
        if (gh >= 0 && gh < HH && gw >= 0 && gw < WW) {
            float xc = sx[R][C];
            float v0 = (gw < WW - 1) ? (sx[R][C + 1] - xc) : 0.f;
            float v1 = (gh < HH - 1) ? (sx[R + 1][C] - xc) : 0.f;
            if (!FIRST) {
                float2 rb = bf2unpack(__ldg(&g_rbar[boff + gh * WW + gw]));
                v0 -= rb.x; v1 -= rb.y;
            }
            v = make_float2(v0, v1);
        }
        sv[R][C] = v;
    }
    __syncthreads();

    const int h = h0 + ty, w = w0 + tx;
    const int i = (int)boff + h * WW + w;

    float2 vc = sv[ty + 1][tx + 1];
    float2 vu = sv[ty][tx + 1];
    float2 vl = sv[ty + 1][tx];
    float2 vd = sv[ty + 2][tx + 1];

    float G0 = vc.x - vu.x;
    float G1 = (w > 0) ? (vc.x - vl.x) : 0.f;
    float G2 = vc.y - vl.y;
    float G3 = (h < HH - 1) ? (vd.y - vc.y) : 0.f;

    float4 u2o = FIRST ? make_float4(0.f, 0.f, 0.f, 0.f)
                       : u2unpack(__ldg(&g_u2[i]));
    float u0 = u2o.x + SIGMAc * G0;
    float u1 = u2o.y + SIGMAc * G1;
    float u2c = u2o.z + SIGMAc * G2;
    float u3 = u2o.w + SIGMAc * G3;

    float lam2 = 0.15f * (float)__ldg(ths);
    float nrm = sqrtf(u0 * u0 + u1 * u1 + u2c * u2c + u3 * u3);
    float sc = 1.f / fmaxf(nrm * (1.f / lam2), 1.f);
    u0 *= sc; u1 *= sc; u2c *= sc; u3 *= sc;

    g_u2[i] = u2pack(u2o.x + RHOc * (u0  - u2o.x),
                     u2o.y + RHOc * (u1  - u2o.y),
                     u2o.z + RHOc * (u2c - u2o.z),
                     u2o.w + RHOc * (u3  - u2o.w));

    if (FIRST) {
        g_x2[i] = sx[ty + 1][tx + 1];
        g_r2[i] = 0u;
    }
}

extern "C" void kernel_launch(void* const* d_in, const int* in_sizes, int n_in,
                              void* d_out, int out_size) {
    const float* y   = (const float*)d_in[0];
    const int*   ths = (const int*)d_in[1];
    float*       out = (float*)d_out;

    dim3 blk(TW, TH, 1);
    dim3 grd(WW / TW, HH / TH, BB);

    // Iteration 1 (specialized: A is a no-op closed form)
    k_B<true><<<grd, blk>>>(y, ths);

    // Iterations 2..9
    for (int it = 1; it < 9; ++it) {
        k_A<false><<<grd, blk>>>(y, ths, nullptr);
        k_B<false><<<grd, blk>>>(y, ths);
    }

    // Iteration 10: only the x path matters; write straight to output.
    k_A<true><<<grd, blk>>>(y, ths, out);
}

// round 8
// speedup vs baseline: 1.0202x; 1.0100x over previous
#include <cuda_runtime.h>
#include <cuda_bf16.h>
#include <math.h>

#define BB 4
#define HH 512
#define WW 512
#define NPIX (BB*HH*WW)
#define TW 32
#define TH 8

#define TAUc   0.01f
#define RHOc   1.99f
#define SIGMAc 1.3888888888888888f   // 1/0.01/72

// u2: 4x bf16 (uint2). r2/rbar: 2x bf16 (u32). x2/xbar: fp32.
typedef uint2 U2raw;
__device__ __align__(16) float    g_x2  [NPIX];
__device__ __align__(16) unsigned g_r2  [NPIX];
__device__ __align__(16) U2raw    g_u2  [NPIX];
__device__ __align__(16) float    g_xbar[NPIX];
__device__ __align__(16) unsigned g_rbar[NPIX];

static __device__ __forceinline__ float4 u2unpack(U2raw r) {
    float2 f0 = __bfloat1622float2(*reinterpret_cast<__nv_bfloat162*>(&r.x));
    float2 f1 = __bfloat1622float2(*reinterpret_cast<__nv_bfloat162*>(&r.y));
    return make_float4(f0.x, f0.y, f1.x, f1.y);
}
static __device__ __forceinline__ U2raw u2pack(float a, float b, float c, float d) {
    __nv_bfloat162 p0 = __floats2bfloat162_rn(a, b);
    __nv_bfloat162 p1 = __floats2bfloat162_rn(c, d);
    U2raw r;
    r.x = *reinterpret_cast<unsigned*>(&p0);
    r.y = *reinterpret_cast<unsigned*>(&p1);
    return r;
}
static __device__ __forceinline__ float2 bf2unpack(unsigned r) {
    return __bfloat1622float2(*reinterpret_cast<__nv_bfloat162*>(&r));
}
static __device__ __forceinline__ unsigned bf2pack(float a, float b) {
    __nv_bfloat162 p = __floats2bfloat162_rn(a, b);
    return *reinterpret_cast<unsigned*>(&p);
}
// Zero-padded accessors into the per-batch u2 plane
static __device__ __forceinline__ float4 ld4(const U2raw* b, int h, int w) {
    if ((unsigned)h < HH && (unsigned)w < WW) return u2unpack(__ldg(b + h * WW + w));
    return make_float4(0.f, 0.f, 0.f, 0.f);
}
static __device__ __forceinline__ float2 ld2xy(const U2raw* b, int h, int w) {
    if ((unsigned)h < HH && (unsigned)w < WW)
        return bf2unpack(__ldg(&(b + h * WW + w)->x));
    return make_float2(0.f, 0.f);
}
static __device__ __forceinline__ float ldc(const U2raw* b, int h, int w, int comp) {
    if ((unsigned)h < HH && (unsigned)w < WW) {
        const __nv_bfloat16* p = reinterpret_cast<const __nv_bfloat16*>(b + h * WW + w);
        return __bfloat162float(__ldg(p + comp));
    }
    return 0.f;
}

// ---------------------------------------------------------------------------
// Kernel A (R5 structure — the measured local optimum): tmp = TAU*eps2_adj(u2)
// recomputed per thread at {p, left(comp0), up(comp1)} via direct predicated
// loads; no smem, no shuffle, no barrier. Then x-prox + r-prox + relaxation.
// r2/rbar in bf16x2. Relies on zero-padding + invariants (u2.y==0 at w=0,
// u2.w==0 at h=H-1).
// ---------------------------------------------------------------------------
template<bool LAST>
__global__ void __launch_bounds__(TW*TH)
k_A(const float* __restrict__ y, const int* __restrict__ ths,
    float* __restrict__ outx) {
    const int w = blockIdx.x * TW + threadIdx.x;
    const int h = blockIdx.y * TH + threadIdx.y;
    const int b = blockIdx.z;
    const int i = (b * HH + h) * WW + w;
    const U2raw* u2b = g_u2 + (size_t)b * HH * WW;

    const float4 c   = u2unpack(__ldg(u2b + h * WW + w));
    const float4 up  = ld4 (u2b, h - 1, w);
    const float4 rt  = ld4 (u2b, h, w + 1);
    const float2 lxy = ld2xy(u2b, h, w - 1);
    const float  Xd  = ldc(u2b, h + 1, w,     0);
    const float  Xdl = ldc(u2b, h + 1, w - 1, 0);
    const float  Zur = ldc(u2b, h - 1, w + 1, 2);
    const float  Wu2 = ldc(u2b, h - 2, w,     3);

    const float t0p = TAUc * (c.x   - Xd  - rt.y + c.y);
    const float t1p = TAUc * (c.z   - rt.z - c.w + up.w);
    const float t0l = TAUc * (lxy.x - Xdl - c.y  + lxy.y);
    const float t1u = TAUc * (up.z  - Zur - up.w + Wu2);

    float div = 0.f;
    if (w < WW - 1) div -= t0p;
    if (w > 0)      div += t0l;
    if (h < HH - 1) div -= t1p;
    if (h > 0)      div += t1u;

    const float x2o = __ldg(&g_x2[i]);
    const float x = (x2o - div + TAUc * __ldg(&y[i])) * (1.f / (1.f + TAUc));
    const float x2n = x2o + RHOc * (x - x2o);

    if (LAST) { outx[i] = x2n; return; }

    g_xbar[i] = 2.f * x - x2o;
    g_x2[i]   = x2n;

    const float lam1 = 0.1f * (float)__ldg(ths);
    const float2 r2o = bf2unpack(__ldg(&g_r2[i]));
    const float rvx = r2o.x + t0p;
    const float rvy = r2o.y + t1p;
    const float nrm = sqrtf(rvx * rvx + rvy * rvy);
    const float s = 1.f - 1.f / fmaxf(nrm * (1.f / (TAUc * lam1)), 1.f);
    const float rx = rvx * s, ry = rvy * s;

    g_rbar[i] = bf2pack(2.f * rx - r2o.x, 2.f * ry - r2o.y);
    g_r2[i]   = bf2pack(r2o.x + RHOc * (rx - r2o.x),
                        r2o.y + RHOc * (ry - r2o.y));
}

// ---------------------------------------------------------------------------
// Kernel B: v = nabla2(xbar) - rbar in shared, then
// u = prox_sigma_g_conj(u2 + SIGMA*eps2(v)) + relaxation (u2/rbar in bf16).
// FIRST iteration: xbar == y, rbar == 0, u2 == 0; also initializes x2=y, r2=0.
// ---------------------------------------------------------------------------
template<bool FIRST>
__global__ void __launch_bounds__(TW*TH)
k_B(const float* __restrict__ y, const int* __restrict__ ths) {
    __shared__ float  sx[TH + 3][TW + 3];
    __shared__ float2 sv[TH + 2][TW + 2];

    const int tx = threadIdx.x, ty = threadIdx.y;
    const int tid = ty * TW + tx;
    const int w0 = blockIdx.x * TW, h0 = blockIdx.y * TH, b = blockIdx.z;
    const size_t boff = (size_t)b * HH * WW;
    const float* xb = FIRST ? (y + boff) : (g_xbar + boff);

    #pragma unroll
    for (int idx = tid; idx < (TH + 3) * (TW + 2); idx += TW * TH) {
        int rr = idx / (TW + 2), cc = idx % (TW + 2);
        int gh = h0 + rr - 1, gw = w0 + cc - 1;
        float v = 0.f;
        if (gh >= 0 && gh < HH && gw >= 0 && gw < WW) v = __ldg(xb + gh * WW + gw);
        sx[rr][cc] = v;
    }
    __syncthreads();

    #pragma unroll
    for (int idx = tid; idx < (TH + 2) * (TW + 1); idx += TW * TH) {
        int R = idx / (TW + 1), C = idx % (TW + 1);
        int gh = h0 + R - 1, gw = w0 + C - 1;
        float2 v = make_float2(0.f, 0.f);
        if (gh >= 0 && gh < HH && gw >= 0 && gw < WW) {
            float xc = sx[R][C];
            float v0 = (gw < WW - 1) ? (sx[R][C + 1] - xc) : 0.f;
            float v1 = (gh < HH - 1) ? (sx[R + 1][C] - xc) : 0.f;
            if (!FIRST) {
                float2 rb = bf2unpack(__ldg(&g_rbar[boff + gh * WW + gw]));
                v0 -= rb.x; v1 -= rb.y;
            }
            v = make_float2(v0, v1);
        }
        sv[R][C] = v;
    }
    __syncthreads();

    const int h = h0 + ty, w = w0 + tx;
    const int i = (int)boff + h * WW + w;

    float2 vc = sv[ty + 1][tx + 1];
    float2 vu = sv[ty][tx + 1];
    float2 vl = sv[ty + 1][tx];
    float2 vd = sv[ty + 2][tx + 1];

    float G0 = vc.x - vu.x;
    float G1 = (w > 0) ? (vc.x - vl.x) : 0.f;
    float G2 = vc.y - vl.y;
    float G3 = (h < HH - 1) ? (vd.y - vc.y) : 0.f;

    float4 u2o = FIRST ? make_float4(0.f, 0.f, 0.f, 0.f)
                       : u2unpack(__ldg(&g_u2[i]));
    float u0 = u2o.x + SIGMAc * G0;
    float u1 = u2o.y + SIGMAc * G1;
    float u2c = u2o.z + SIGMAc * G2;
    float u3 = u2o.w + SIGMAc * G3;

    float lam2 = 0.15f * (float)__ldg(ths);
    float nrm = sqrtf(u0 * u0 + u1 * u1 + u2c * u2c + u3 * u3);
    float sc = 1.f / fmaxf(nrm * (1.f / lam2), 1.f);
    u0 *= sc; u1 *= sc; u2c *= sc; u3 *= sc;

    g_u2[i] = u2pack(u2o.x + RHOc * (u0  - u2o.x),
                     u2o.y + RHOc * (u1  - u2o.y),
                     u2o.z + RHOc * (u2c - u2o.z),
                     u2o.w + RHOc * (u3  - u2o.w));

    if (FIRST) {
        g_x2[i] = sx[ty + 1][tx + 1];
        g_r2[i] = 0u;
    }
}

extern "C" void kernel_launch(void* const* d_in, const int* in_sizes, int n_in,
                              void* d_out, int out_size) {
    const float* y   = (const float*)d_in[0];
    const int*   ths = (const int*)d_in[1];
    float*       out = (float*)d_out;

    dim3 blk(TW, TH, 1);
    dim3 grd(WW / TW, HH / TH, BB);

    // Iteration 1 (specialized: A is a no-op closed form)
    k_B<true><<<grd, blk>>>(y, ths);

    // Iterations 2..9
    for (int it = 1; it < 9; ++it) {
        k_A<false><<<grd, blk>>>(y, ths, nullptr);
        k_B<false><<<grd, blk>>>(y, ths);
    }

    // Iteration 10: only the x path matters; write straight to output.
    k_A<true><<<grd, blk>>>(y, ths, out);
}

// round 9
// speedup vs baseline: 1.0945x; 1.0728x over previous
#include <cuda_runtime.h>
#include <cuda_bf16.h>
#include <math.h>

#define BB 4
#define HH 512
#define WW 512
#define NPIX (BB*HH*WW)
#define TW 32
#define TH 8

#define TAUc   0.01f
#define RHOc   1.99f
#define SIGMAc 1.3888888888888888f   // 1/0.01/72

// u2: 4x bf16 (uint2). r2/rbar: 2x bf16 (u32). x2/xbar: fp32.
typedef uint2 U2raw;
__device__ __align__(16) float    g_x2  [NPIX];
__device__ __align__(16) unsigned g_r2  [NPIX];
__device__ __align__(16) U2raw    g_u2  [NPIX];
__device__ __align__(16) float    g_xbar[NPIX];
__device__ __align__(16) unsigned g_rbar[NPIX];

static __device__ __forceinline__ float4 u2unpack(U2raw r) {
    float2 f0 = __bfloat1622float2(*reinterpret_cast<__nv_bfloat162*>(&r.x));
    float2 f1 = __bfloat1622float2(*reinterpret_cast<__nv_bfloat162*>(&r.y));
    return make_float4(f0.x, f0.y, f1.x, f1.y);
}
static __device__ __forceinline__ U2raw u2pack(float a, float b, float c, float d) {
    __nv_bfloat162 p0 = __floats2bfloat162_rn(a, b);
    __nv_bfloat162 p1 = __floats2bfloat162_rn(c, d);
    U2raw r;
    r.x = *reinterpret_cast<unsigned*>(&p0);
    r.y = *reinterpret_cast<unsigned*>(&p1);
    return r;
}
static __device__ __forceinline__ float2 bf2unpack(unsigned r) {
    return __bfloat1622float2(*reinterpret_cast<__nv_bfloat162*>(&r));
}
static __device__ __forceinline__ unsigned bf2pack(float a, float b) {
    __nv_bfloat162 p = __floats2bfloat162_rn(a, b);
    return *reinterpret_cast<unsigned*>(&p);
}
static __device__ __forceinline__ float bfld(const __nv_bfloat16* p) {
    return __bfloat162float(__ldg(p));
}

// ---------------------------------------------------------------------------
// Kernel A, 2-row vertical coarsening (coalescing-preserving): each thread
// handles pixels (h, w) and (h+1, w). Stencil overlaps shared in registers:
//   Xd(r0)=c1.x, Xdl(r0)=l1.x, Zur(r1)=rt0.z, Wu2(r1)=upzw.y, t1u(r1)=t1p(r0).
// Then x-prox + r-prox + relaxation per row. r2/rbar bf16x2.
// Relies on zero-padding + invariants u2.y==0 at w=0, u2.w==0 at h=H-1.
// ---------------------------------------------------------------------------
template<bool LAST>
__global__ void __launch_bounds__(256)
k_A(const float* __restrict__ y, const int* __restrict__ ths,
    float* __restrict__ outx) {
    const int w = blockIdx.x * 32 + threadIdx.x;
    const int h = (blockIdx.y * 8 + threadIdx.y) * 2;      // even, <= 510
    const int b = blockIdx.z;
    const int i = (b * HH + h) * WW + w;
    const U2raw* p0 = g_u2 + (size_t)b * HH * WW + h * WW + w;

    const float4 c0 = u2unpack(__ldg(p0));
    const float4 c1 = u2unpack(__ldg(p0 + WW));
    float4 rt0 = make_float4(0.f,0.f,0.f,0.f), rt1 = rt0;
    if (w < WW - 1) {
        rt0 = u2unpack(__ldg(p0 + 1));
        rt1 = u2unpack(__ldg(p0 + WW + 1));
    }
    float2 upzw = make_float2(0.f, 0.f);
    if (h > 0) upzw = bf2unpack(__ldg(&(p0 - WW)->y));
    float2 l0 = make_float2(0.f, 0.f), l1 = l0;
    if (w > 0) {
        l0 = bf2unpack(__ldg(&(p0 - 1)->x));
        l1 = bf2unpack(__ldg(&(p0 + WW - 1)->x));
    }
    float Xd1 = 0.f, Xdl1 = 0.f;
    if (h + 2 < HH) {
        const __nv_bfloat16* q = (const __nv_bfloat16*)(p0 + 2 * WW);
        Xd1 = bfld(q);
        if (w > 0) Xdl1 = bfld(q - 4);
    }
    float Zur0 = 0.f;
    if (h > 0 && w < WW - 1)
        Zur0 = bfld(((const __nv_bfloat16*)(p0 - WW + 1)) + 2);
    float Wu20 = 0.f;
    if (h >= 2)
        Wu20 = bfld(((const __nv_bfloat16*)(p0 - 2 * WW)) + 3);

    // tmp values
    const float t0p0 = TAUc * (c0.x - c1.x  - rt0.y + c0.y);
    const float t1p0 = TAUc * (c0.z - rt0.z - c0.w  + upzw.y);
    const float t0l0 = TAUc * (l0.x - l1.x  - c0.y  + l0.y);
    const float t1u0 = TAUc * (upzw.x - Zur0 - upzw.y + Wu20);
    const float t0p1 = TAUc * (c1.x - Xd1   - rt1.y + c1.y);
    const float t1p1 = TAUc * (c1.z - rt1.z - c1.w  + c0.w);
    const float t0l1 = TAUc * (l1.x - Xdl1  - c1.y  + l1.y);
    const float t1u1 = t1p0;

    float div0 = -t1p0;                 // h < HH-1 always for even h <= 510
    if (w < WW - 1) div0 -= t0p0;
    if (w > 0)      div0 += t0l0;
    if (h > 0)      div0 += t1u0;

    float div1 = t1u1;                  // h+1 > 0 always
    if (w < WW - 1)  div1 -= t0p1;
    if (w > 0)       div1 += t0l1;
    if (h + 2 < HH)  div1 -= t1p1;

    const float inv = 1.f / (1.f + TAUc);
    const float x2o0 = __ldg(&g_x2[i]);
    const float x2o1 = __ldg(&g_x2[i + WW]);
    const float x0 = (x2o0 - div0 + TAUc * __ldg(&y[i]))      * inv;
    const float x1 = (x2o1 - div1 + TAUc * __ldg(&y[i + WW])) * inv;
    const float x2n0 = x2o0 + RHOc * (x0 - x2o0);
    const float x2n1 = x2o1 + RHOc * (x1 - x2o1);

    if (LAST) {
        outx[i]      = x2n0;
        outx[i + WW] = x2n1;
        return;
    }

    g_xbar[i]      = 2.f * x0 - x2o0;
    g_xbar[i + WW] = 2.f * x1 - x2o1;
    g_x2[i]        = x2n0;
    g_x2[i + WW]   = x2n1;

    const float lam1 = 0.1f * (float)__ldg(ths);
    const float itl = 1.f / (TAUc * lam1);
    {
        const float2 r2o = bf2unpack(__ldg(&g_r2[i]));
        const float rvx = r2o.x + t0p0, rvy = r2o.y + t1p0;
        const float s = 1.f - 1.f / fmaxf(sqrtf(rvx*rvx + rvy*rvy) * itl, 1.f);
        const float rx = rvx * s, ry = rvy * s;
        g_rbar[i] = bf2pack(2.f * rx - r2o.x, 2.f * ry - r2o.y);
        g_r2[i]   = bf2pack(r2o.x + RHOc * (rx - r2o.x),
                            r2o.y + RHOc * (ry - r2o.y));
    }
    {
        const float2 r2o = bf2unpack(__ldg(&g_r2[i + WW]));
        const float rvx = r2o.x + t0p1, rvy = r2o.y + t1p1;
        const float s = 1.f - 1.f / fmaxf(sqrtf(rvx*rvx + rvy*rvy) * itl, 1.f);
        const float rx = rvx * s, ry = rvy * s;
        g_rbar[i + WW] = bf2pack(2.f * rx - r2o.x, 2.f * ry - r2o.y);
        g_r2[i + WW]   = bf2pack(r2o.x + RHOc * (rx - r2o.x),
                                 r2o.y + RHOc * (ry - r2o.y));
    }
}

// ---------------------------------------------------------------------------
// Kernel B (unchanged): v = nabla2(xbar) - rbar in shared, then
// u = prox_sigma_g_conj(u2 + SIGMA*eps2(v)) + relaxation (u2/rbar bf16).
// FIRST iteration: xbar == y, rbar == 0, u2 == 0; also initializes x2=y, r2=0.
// ---------------------------------------------------------------------------
template<bool FIRST>
__global__ void __launch_bounds__(TW*TH)
k_B(const float* __restrict__ y, const int* __restrict__ ths) {
    __shared__ float  sx[TH + 3][TW + 3];
    __shared__ float2 sv[TH + 2][TW + 2];

    const int tx = threadIdx.x, ty = threadIdx.y;
    const int tid = ty * TW + tx;
    const int w0 = blockIdx.x * TW, h0 = blockIdx.y * TH, b = blockIdx.z;
    const size_t boff = (size_t)b * HH * WW;
    const float* xb = FIRST ? (y + boff) : (g_xbar + boff);

    #pragma unroll
    for (int idx = tid; idx < (TH + 3) * (TW + 2); idx += TW * TH) {
        int rr = idx / (TW + 2), cc = idx % (TW + 2);
        int gh = h0 + rr - 1, gw = w0 + cc - 1;
        float v = 0.f;
        if (gh >= 0 && gh < HH && gw >= 0 && gw < WW) v = __ldg(xb + gh * WW + gw);
        sx[rr][cc] = v;
    }
    __syncthreads();

    #pragma unroll
    for (int idx = tid; idx < (TH + 2) * (TW + 1); idx += TW * TH) {
        int R = idx / (TW + 1), C = idx % (TW + 1);
        int gh = h0 + R - 1, gw = w0 + C - 1;
        float2 v = make_float2(0.f, 0.f);
        if (gh >= 0 && gh < HH && gw >= 0 && gw < WW) {
            float xc = sx[R][C];
            float v0 = (gw < WW - 1) ? (sx[R][C + 1] - xc) : 0.f;
            float v1 = (gh < HH - 1) ? (sx[R + 1][C] - xc) : 0.f;
            if (!FIRST) {
                float2 rb = bf2unpack(__ldg(&g_rbar[boff + gh * WW + gw]));
                v0 -= rb.x; v1 -= rb.y;
            }
            v = make_float2(v0, v1);
        }
        sv[R][C] = v;
    }
    __syncthreads();

    const int h = h0 + ty, w = w0 + tx;
    const int i = (int)boff + h * WW + w;

    float2 vc = sv[ty + 1][tx + 1];
    float2 vu = sv[ty][tx + 1];
    float2 vl = sv[ty + 1][tx];
    float2 vd = sv[ty + 2][tx + 1];

    float G0 = vc.x - vu.x;
    float G1 = (w > 0) ? (vc.x - vl.x) : 0.f;
    float G2 = vc.y - vl.y;
    float G3 = (h < HH - 1) ? (vd.y - vc.y) : 0.f;

    float4 u2o = FIRST ? make_float4(0.f, 0.f, 0.f, 0.f)
                       : u2unpack(__ldg(&g_u2[i]));
    float u0 = u2o.x + SIGMAc * G0;
    float u1 = u2o.y + SIGMAc * G1;
    float u2c = u2o.z + SIGMAc * G2;
    float u3 = u2o.w + SIGMAc * G3;

    float lam2 = 0.15f * (float)__ldg(ths);
    float nrm = sqrtf(u0 * u0 + u1 * u1 + u2c * u2c + u3 * u3);
    float sc = 1.f / fmaxf(nrm * (1.f / lam2), 1.f);
    u0 *= sc; u1 *= sc; u2c *= sc; u3 *= sc;

    g_u2[i] = u2pack(u2o.x + RHOc * (u0  - u2o.x),
                     u2o.y + RHOc * (u1  - u2o.y),
                     u2o.z + RHOc * (u2c - u2o.z),
                     u2o.w + RHOc * (u3  - u2o.w));

    if (FIRST) {
        g_x2[i] = sx[ty + 1][tx + 1];
        g_r2[i] = 0u;
    }
}

extern "C" void kernel_launch(void* const* d_in, const int* in_sizes, int n_in,
                              void* d_out, int out_size) {
    const float* y   = (const float*)d_in[0];
    const int*   ths = (const int*)d_in[1];
    float*       out = (float*)d_out;

    dim3 blkA(32, 8, 1);
    dim3 grdA(WW / 32, HH / 16, BB);     // 2 rows per thread
    dim3 blkB(TW, TH, 1);
    dim3 grdB(WW / TW, HH / TH, BB);

    // Iteration 1 (specialized: A is a no-op closed form)
    k_B<true><<<grdB, blkB>>>(y, ths);

    // Iterations 2..9
    for (int it = 1; it < 9; ++it) {
        k_A<false><<<grdA, blkA>>>(y, ths, nullptr);
        k_B<false><<<grdB, blkB>>>(y, ths);
    }

    // Iteration 10: only the x path matters; write straight to output.
    k_A<true><<<grdA, blkA>>>(y, ths, out);
}